// round 2
// baseline (speedup 1.0000x reference)
#include <cuda_runtime.h>
#include <cuda_bf16.h>

// Problem constants
#define H      2048     // hidden
#define E      64       // experts
#define NTOK   16384    // 4*4096 tokens
#define TM     128      // tokens per block
#define KT     64       // k-tile
#define NBLK   (NTOK/TM)  // 128
#define XS_STRIDE 132   // padded row stride for x tile [KT][XS_STRIDE]
#define SCORE_STRIDE 67 // padded row stride for logits/scores [TM][67]

typedef unsigned long long ull;

// Deterministic per-block partial buffers (no float atomics).
__device__ float g_part_load[NBLK * E];
__device__ float g_part_z[NBLK];

__device__ __forceinline__ ull pack2(float a, float b) {
    ull r;
    asm("mov.b64 %0, {%1,%2};" : "=l"(r) : "f"(a), "f"(b));
    return r;
}
__device__ __forceinline__ void unpack2(ull v, float& a, float& b) {
    asm("mov.b64 {%0,%1}, %2;" : "=f"(a), "=f"(b) : "l"(v));
}
__device__ __forceinline__ void fma2(ull& d, ull a, ull b) {
    // packed f32x2 FMA: d.lo += a.lo*b.lo ; d.hi += a.hi*b.hi
    asm("fma.rn.f32x2 %0, %1, %2, %0;" : "+l"(d) : "l"(a), "l"(b));
}

__global__ __launch_bounds__(256) void gate_kernel(
    const float* __restrict__ x,
    const float* __restrict__ W,
    float* __restrict__ out,
    int out_size)
{
    // smem: x tile [KT][XS_STRIDE] = 8448 floats, w tile [KT][E] = 4096 floats.
    // Epilogue reuses the whole region as scores [TM][SCORE_STRIDE] = 8576 floats.
    __shared__ __align__(16) float sm[XS_STRIDE * KT + KT * E]; // 12544 floats
    __shared__ float inv_s[TM];
    __shared__ float lse2_s[TM];

    float* x_s = sm;
    float* w_s = sm + XS_STRIDE * KT;

    const int tid = threadIdx.x;
    const int blk = blockIdx.x;
    const int rowBase = blk * TM;

    // ---- load-index precompute ----
    // x tile: 128 tokens x 64 k = 2048 float4s; thread gets 8 consecutive float4s
    const int lt_tok = tid >> 1;            // token within tile (0..127)
    const int lt_k0  = (tid & 1) * 32;      // k offset base (0 or 32)
    const float4* xg = (const float4*)(x + (size_t)(rowBase + lt_tok) * H + lt_k0);
    // w tile: 64 e x 64 k = 1024 float4s; thread gets 4 consecutive float4s
    const int e_w     = tid >> 2;           // expert row (0..63)
    const int k4base  = (tid & 3) * 4;      // float4 index within 16-per-row
    const float4* wg = (const float4*)(W + (size_t)e_w * H);

    // ---- compute mapping ----
    const int tx = tid & 15;   // expert group: experts tx*4..tx*4+3
    const int ty = tid >> 4;   // token group:  tokens ty*8..ty*8+7
    const int e0 = tx * 4;
    const int t0 = ty * 8;

    ull acc[4][4];             // [token-pair][expert]; packed (even tok, odd tok)
    #pragma unroll
    for (int a = 0; a < 4; a++)
        #pragma unroll
        for (int b = 0; b < 4; b++) acc[a][b] = 0ULL;

    float4 xr[8], wr[4];

    // ---- prologue: load tile 0 into regs, store to smem ----
    #pragma unroll
    for (int j = 0; j < 8; j++) xr[j] = xg[j];
    #pragma unroll
    for (int j = 0; j < 4; j++) wr[j] = wg[k4base + j];
    #pragma unroll
    for (int j = 0; j < 8; j++) {
        int kof = lt_k0 + j * 4;
        x_s[(kof + 0) * XS_STRIDE + lt_tok] = xr[j].x;
        x_s[(kof + 1) * XS_STRIDE + lt_tok] = xr[j].y;
        x_s[(kof + 2) * XS_STRIDE + lt_tok] = xr[j].z;
        x_s[(kof + 3) * XS_STRIDE + lt_tok] = xr[j].w;
    }
    #pragma unroll
    for (int j = 0; j < 4; j++) {
        int kof = (k4base + j) * 4;
        w_s[(kof + 0) * E + e_w] = wr[j].x;
        w_s[(kof + 1) * E + e_w] = wr[j].y;
        w_s[(kof + 2) * E + e_w] = wr[j].z;
        w_s[(kof + 3) * E + e_w] = wr[j].w;
    }
    __syncthreads();

    const int NKT = H / KT;  // 32
    for (int kt = 0; kt < NKT; kt++) {
        // prefetch next tile into registers (overlaps with compute)
        if (kt + 1 < NKT) {
            int f4base = (kt + 1) * (KT / 4);
            #pragma unroll
            for (int j = 0; j < 8; j++) xr[j] = xg[f4base + j];
            #pragma unroll
            for (int j = 0; j < 4; j++) wr[j] = wg[f4base + k4base + j];
        }

        // ---- compute over this k-tile ----
        #pragma unroll 2
        for (int kk = 0; kk < KT; kk++) {
            const ull* xp = (const ull*)(x_s + kk * XS_STRIDE + t0);
            ull xp0 = xp[0], xp1 = xp[1], xp2 = xp[2], xp3 = xp[3];
            float4 w4 = *(const float4*)(w_s + kk * E + e0);
            ull wd0 = pack2(w4.x, w4.x);
            ull wd1 = pack2(w4.y, w4.y);
            ull wd2 = pack2(w4.z, w4.z);
            ull wd3 = pack2(w4.w, w4.w);
            fma2(acc[0][0], xp0, wd0); fma2(acc[0][1], xp0, wd1);
            fma2(acc[0][2], xp0, wd2); fma2(acc[0][3], xp0, wd3);
            fma2(acc[1][0], xp1, wd0); fma2(acc[1][1], xp1, wd1);
            fma2(acc[1][2], xp1, wd2); fma2(acc[1][3], xp1, wd3);
            fma2(acc[2][0], xp2, wd0); fma2(acc[2][1], xp2, wd1);
            fma2(acc[2][2], xp2, wd2); fma2(acc[2][3], xp2, wd3);
            fma2(acc[3][0], xp3, wd0); fma2(acc[3][1], xp3, wd1);
            fma2(acc[3][2], xp3, wd2); fma2(acc[3][3], xp3, wd3);
        }
        __syncthreads();

        if (kt + 1 < NKT) {
            #pragma unroll
            for (int j = 0; j < 8; j++) {
                int kof = lt_k0 + j * 4;
                x_s[(kof + 0) * XS_STRIDE + lt_tok] = xr[j].x;
                x_s[(kof + 1) * XS_STRIDE + lt_tok] = xr[j].y;
                x_s[(kof + 2) * XS_STRIDE + lt_tok] = xr[j].z;
                x_s[(kof + 3) * XS_STRIDE + lt_tok] = xr[j].w;
            }
            #pragma unroll
            for (int j = 0; j < 4; j++) {
                int kof = (k4base + j) * 4;
                w_s[(kof + 0) * E + e_w] = wr[j].x;
                w_s[(kof + 1) * E + e_w] = wr[j].y;
                w_s[(kof + 2) * E + e_w] = wr[j].z;
                w_s[(kof + 3) * E + e_w] = wr[j].w;
            }
            __syncthreads();
        }
    }

    // ---- epilogue: write logits to smem (reuse tile memory) ----
    #pragma unroll
    for (int tp = 0; tp < 4; tp++) {
        #pragma unroll
        for (int j = 0; j < 4; j++) {
            float lo, hi;
            unpack2(acc[tp][j], lo, hi);
            int t = t0 + 2 * tp;
            sm[t * SCORE_STRIDE + e0 + j]       = lo;
            sm[(t + 1) * SCORE_STRIDE + e0 + j] = hi;
        }
    }
    __syncthreads();

    // ---- per-token softmax / top-2 / outputs ----
    if (tid < TM) {
        const int t = tid;
        float* row = sm + t * SCORE_STRIDE;
        float m1 = -1e30f, m2 = -1e30f;
        int i1 = 0, i2 = 0;
        #pragma unroll 4
        for (int e = 0; e < E; e++) {
            float v = row[e];
            if (v > m1) { m2 = m1; i2 = i1; m1 = v; i1 = e; }
            else if (v > m2) { m2 = v; i2 = e; }
        }
        float s = 0.0f;
        #pragma unroll 4
        for (int e = 0; e < E; e++) {
            float u = __expf(row[e] - m1);
            row[e] = u;            // store unnormalized score
            s += u;
        }
        float inv = 1.0f / s;
        inv_s[t] = inv;
        float lse = m1 + __logf(s);
        lse2_s[t] = lse * lse;

        // Reference: top_scores = softmax(top_k(softmax_probs)).
        // p1, p2 are the top-2 softmax PROBABILITIES:
        //   p1 = exp(m1-m1)*inv = inv,  p2 = exp(m2-m1)*inv
        // then r1 = exp(p1)/(exp(p1)+exp(p2)) = 1/(1+exp(p2-p1)), r2 = 1-r1.
        float p1 = inv;
        float p2 = __expf(m2 - m1) * inv;
        float r2 = 1.0f / (1.0f + __expf(p1 - p2));
        float r1 = 1.0f - r2;

        int gt = rowBase + t;
        if (2 * gt + 1 < out_size) {
            out[2 * gt]     = r1;
            out[2 * gt + 1] = r2;
        }
        int ib = 2 * NTOK;  // idx region base
        if (ib + 2 * gt + 1 < out_size) {
            out[ib + 2 * gt]     = (float)i1;
            out[ib + 2 * gt + 1] = (float)i2;
        }
    }
    __syncthreads();

    // ---- per-expert partial score sums (for load-balance loss) ----
    if (tid < E) {
        const int e = tid;
        float s = 0.0f;
        #pragma unroll 4
        for (int t = 0; t < TM; t++)
            s += sm[t * SCORE_STRIDE + e] * inv_s[t];
        g_part_load[blk * E + e] = s;
    }
    if (tid == E) {
        float z = 0.0f;
        #pragma unroll 4
        for (int t = 0; t < TM; t++) z += lse2_s[t];
        g_part_z[blk] = z;
    }
}

__global__ void reduce_kernel(float* __restrict__ out, int out_size)
{
    __shared__ float red[E];
    int e = threadIdx.x;  // 0..63
    float S = 0.0f;
    for (int b = 0; b < NBLK; b++) S += g_part_load[b * E + e];
    float mean = S / (float)NTOK;
    float d = mean - (1.0f / (float)E);
    red[e] = d * d;
    __syncthreads();
    if (e == 0) {
        float lb = 0.0f;
        #pragma unroll
        for (int i = 0; i < E; i++) lb += red[i];
        float z = 0.0f;
        for (int b = 0; b < NBLK; b++) z += g_part_z[b];
        float total = 0.01f * lb + 1e-4f * (z / (float)NTOK);
        if (out_size > 4 * NTOK) out[4 * NTOK] = total;
    }
}

extern "C" void kernel_launch(void* const* d_in, const int* in_sizes, int n_in,
                              void* d_out, int out_size)
{
    const float* x = (const float*)d_in[0];   // [4,4096,2048] f32
    const float* W = (const float*)d_in[1];   // [64,2048] f32
    float* out = (float*)d_out;

    gate_kernel<<<NBLK, 256>>>(x, W, out, out_size);
    reduce_kernel<<<1, E>>>(out, out_size);
}

// round 3
// speedup vs baseline: 1.0044x; 1.0044x over previous
#include <cuda_runtime.h>
#include <cuda_bf16.h>

// Problem constants
#define H      2048     // hidden
#define E      64       // experts
#define NTOK   16384    // 4*4096 tokens
#define TM     128      // tokens per block
#define KT     64       // k-tile
#define NBLK   (NTOK/TM)  // 128
#define XS_STRIDE 132   // padded row stride for x tile [KT][XS_STRIDE]
#define SCORE_STRIDE 67 // padded row stride for logits/scores [TM][67]

typedef unsigned long long ull;

// Deterministic per-block partial buffers (no float atomics).
__device__ float g_part_load[NBLK * E];
__device__ float g_part_z[NBLK];

__device__ __forceinline__ ull pack2(float a, float b) {
    ull r;
    asm("mov.b64 %0, {%1,%2};" : "=l"(r) : "f"(a), "f"(b));
    return r;
}
__device__ __forceinline__ void unpack2(ull v, float& a, float& b) {
    asm("mov.b64 {%0,%1}, %2;" : "=f"(a), "=f"(b) : "l"(v));
}
__device__ __forceinline__ void fma2(ull& d, ull a, ull b) {
    // packed f32x2 FMA: d.lo += a.lo*b.lo ; d.hi += a.hi*b.hi
    asm("fma.rn.f32x2 %0, %1, %2, %0;" : "+l"(d) : "l"(a), "l"(b));
}

__global__ __launch_bounds__(256) void gate_kernel(
    const float* __restrict__ x,
    const float* __restrict__ W,
    float* __restrict__ out,
    int out_size)
{
    // smem: x tile [KT][XS_STRIDE] = 8448 floats, w tile [KT][E] = 4096 floats.
    // Epilogue reuses the whole region as scores [TM][SCORE_STRIDE] = 8576 floats.
    __shared__ __align__(16) float sm[XS_STRIDE * KT + KT * E]; // 12544 floats
    __shared__ float inv_s[TM];
    __shared__ float lse2_s[TM];

    float* x_s = sm;
    float* w_s = sm + XS_STRIDE * KT;

    const int tid = threadIdx.x;
    const int blk = blockIdx.x;
    const int rowBase = blk * TM;

    // ---- load-index precompute ----
    // x tile: 128 tokens x 64 k = 2048 float4s; thread gets 8 consecutive float4s
    const int lt_tok = tid >> 1;            // token within tile (0..127)
    const int lt_k0  = (tid & 1) * 32;      // k offset base (0 or 32)
    const float4* xg = (const float4*)(x + (size_t)(rowBase + lt_tok) * H + lt_k0);
    // w tile: 64 e x 64 k = 1024 float4s; thread gets 4 consecutive float4s
    const int e_w     = tid >> 2;           // expert row (0..63)
    const int k4base  = (tid & 3) * 4;      // float4 index within 16-per-row
    const float4* wg = (const float4*)(W + (size_t)e_w * H);

    // ---- compute mapping ----
    const int tx = tid & 15;   // expert group: experts tx*4..tx*4+3
    const int ty = tid >> 4;   // token group:  tokens ty*8..ty*8+7
    const int e0 = tx * 4;
    const int t0 = ty * 8;

    ull acc[4][4];             // [token-pair][expert]; packed (even tok, odd tok)
    #pragma unroll
    for (int a = 0; a < 4; a++)
        #pragma unroll
        for (int b = 0; b < 4; b++) acc[a][b] = 0ULL;

    float4 xr[8], wr[4];

    // ---- prologue: load tile 0 into regs, store to smem ----
    #pragma unroll
    for (int j = 0; j < 8; j++) xr[j] = xg[j];
    #pragma unroll
    for (int j = 0; j < 4; j++) wr[j] = wg[k4base + j];
    #pragma unroll
    for (int j = 0; j < 8; j++) {
        int kof = lt_k0 + j * 4;
        x_s[(kof + 0) * XS_STRIDE + lt_tok] = xr[j].x;
        x_s[(kof + 1) * XS_STRIDE + lt_tok] = xr[j].y;
        x_s[(kof + 2) * XS_STRIDE + lt_tok] = xr[j].z;
        x_s[(kof + 3) * XS_STRIDE + lt_tok] = xr[j].w;
    }
    #pragma unroll
    for (int j = 0; j < 4; j++) {
        int kof = (k4base + j) * 4;
        w_s[(kof + 0) * E + e_w] = wr[j].x;
        w_s[(kof + 1) * E + e_w] = wr[j].y;
        w_s[(kof + 2) * E + e_w] = wr[j].z;
        w_s[(kof + 3) * E + e_w] = wr[j].w;
    }
    __syncthreads();

    const int NKT = H / KT;  // 32
    for (int kt = 0; kt < NKT; kt++) {
        // prefetch next tile into registers (overlaps with compute)
        if (kt + 1 < NKT) {
            int f4base = (kt + 1) * (KT / 4);
            #pragma unroll
            for (int j = 0; j < 8; j++) xr[j] = xg[f4base + j];
            #pragma unroll
            for (int j = 0; j < 4; j++) wr[j] = wg[f4base + k4base + j];
        }

        // ---- compute over this k-tile ----
        #pragma unroll 2
        for (int kk = 0; kk < KT; kk++) {
            const ull* xp = (const ull*)(x_s + kk * XS_STRIDE + t0);
            ull xp0 = xp[0], xp1 = xp[1], xp2 = xp[2], xp3 = xp[3];
            float4 w4 = *(const float4*)(w_s + kk * E + e0);
            ull wd0 = pack2(w4.x, w4.x);
            ull wd1 = pack2(w4.y, w4.y);
            ull wd2 = pack2(w4.z, w4.z);
            ull wd3 = pack2(w4.w, w4.w);
            fma2(acc[0][0], xp0, wd0); fma2(acc[0][1], xp0, wd1);
            fma2(acc[0][2], xp0, wd2); fma2(acc[0][3], xp0, wd3);
            fma2(acc[1][0], xp1, wd0); fma2(acc[1][1], xp1, wd1);
            fma2(acc[1][2], xp1, wd2); fma2(acc[1][3], xp1, wd3);
            fma2(acc[2][0], xp2, wd0); fma2(acc[2][1], xp2, wd1);
            fma2(acc[2][2], xp2, wd2); fma2(acc[2][3], xp2, wd3);
            fma2(acc[3][0], xp3, wd0); fma2(acc[3][1], xp3, wd1);
            fma2(acc[3][2], xp3, wd2); fma2(acc[3][3], xp3, wd3);
        }
        __syncthreads();

        if (kt + 1 < NKT) {
            #pragma unroll
            for (int j = 0; j < 8; j++) {
                int kof = lt_k0 + j * 4;
                x_s[(kof + 0) * XS_STRIDE + lt_tok] = xr[j].x;
                x_s[(kof + 1) * XS_STRIDE + lt_tok] = xr[j].y;
                x_s[(kof + 2) * XS_STRIDE + lt_tok] = xr[j].z;
                x_s[(kof + 3) * XS_STRIDE + lt_tok] = xr[j].w;
            }
            #pragma unroll
            for (int j = 0; j < 4; j++) {
                int kof = (k4base + j) * 4;
                w_s[(kof + 0) * E + e_w] = wr[j].x;
                w_s[(kof + 1) * E + e_w] = wr[j].y;
                w_s[(kof + 2) * E + e_w] = wr[j].z;
                w_s[(kof + 3) * E + e_w] = wr[j].w;
            }
            __syncthreads();
        }
    }

    // ---- epilogue: write logits to smem (reuse tile memory) ----
    #pragma unroll
    for (int tp = 0; tp < 4; tp++) {
        #pragma unroll
        for (int j = 0; j < 4; j++) {
            float lo, hi;
            unpack2(acc[tp][j], lo, hi);
            int t = t0 + 2 * tp;
            sm[t * SCORE_STRIDE + e0 + j]       = lo;
            sm[(t + 1) * SCORE_STRIDE + e0 + j] = hi;
        }
    }
    __syncthreads();

    // ---- per-token softmax / top-2 / outputs ----
    if (tid < TM) {
        const int t = tid;
        float* row = sm + t * SCORE_STRIDE;
        float m1 = -1e30f, m2 = -1e30f;
        int i1 = 0, i2 = 0;
        #pragma unroll 4
        for (int e = 0; e < E; e++) {
            float v = row[e];
            if (v > m1) { m2 = m1; i2 = i1; m1 = v; i1 = e; }
            else if (v > m2) { m2 = v; i2 = e; }
        }
        float s = 0.0f;
        #pragma unroll 4
        for (int e = 0; e < E; e++) {
            float u = __expf(row[e] - m1);
            row[e] = u;            // store unnormalized score
            s += u;
        }
        float inv = 1.0f / s;
        inv_s[t] = inv;
        float lse = m1 + __logf(s);
        lse2_s[t] = lse * lse;

        // Reference: top_scores = softmax(top_k(softmax_probs)).
        // p1, p2 are the top-2 softmax PROBABILITIES:
        //   p1 = exp(m1-m1)*inv = inv,  p2 = exp(m2-m1)*inv
        // then r1 = exp(p1)/(exp(p1)+exp(p2)) = 1/(1+exp(p2-p1)), r2 = 1-r1.
        float p1 = inv;
        float p2 = __expf(m2 - m1) * inv;
        float r2 = 1.0f / (1.0f + __expf(p1 - p2));
        float r1 = 1.0f - r2;

        int gt = rowBase + t;
        if (2 * gt + 1 < out_size) {
            out[2 * gt]     = r1;
            out[2 * gt + 1] = r2;
        }
        int ib = 2 * NTOK;  // idx region base
        if (ib + 2 * gt + 1 < out_size) {
            out[ib + 2 * gt]     = (float)i1;
            out[ib + 2 * gt + 1] = (float)i2;
        }
    }
    __syncthreads();

    // ---- per-expert partial score sums (for load-balance loss) ----
    if (tid < E) {
        const int e = tid;
        float s = 0.0f;
        #pragma unroll 4
        for (int t = 0; t < TM; t++)
            s += sm[t * SCORE_STRIDE + e] * inv_s[t];
        g_part_load[blk * E + e] = s;
    }
    if (tid == E) {
        float z = 0.0f;
        #pragma unroll 4
        for (int t = 0; t < TM; t++) z += lse2_s[t];
        g_part_z[blk] = z;
    }
}

__global__ void reduce_kernel(float* __restrict__ out, int out_size)
{
    __shared__ float red[E];
    int e = threadIdx.x;  // 0..63
    float S = 0.0f;
    for (int b = 0; b < NBLK; b++) S += g_part_load[b * E + e];
    float mean = S / (float)NTOK;
    float d = mean - (1.0f / (float)E);
    red[e] = d * d;
    __syncthreads();
    if (e == 0) {
        float lb = 0.0f;
        #pragma unroll
        for (int i = 0; i < E; i++) lb += red[i];
        float z = 0.0f;
        for (int b = 0; b < NBLK; b++) z += g_part_z[b];
        float total = 0.01f * lb + 1e-4f * (z / (float)NTOK);
        if (out_size > 4 * NTOK) out[4 * NTOK] = total;
    }
}

extern "C" void kernel_launch(void* const* d_in, const int* in_sizes, int n_in,
                              void* d_out, int out_size)
{
    const float* x = (const float*)d_in[0];   // [4,4096,2048] f32
    const float* W = (const float*)d_in[1];   // [64,2048] f32
    float* out = (float*)d_out;

    gate_kernel<<<NBLK, 256>>>(x, W, out, out_size);
    reduce_kernel<<<1, E>>>(out, out_size);
}

// round 5
// speedup vs baseline: 1.8743x; 1.8660x over previous
#include <cuda_runtime.h>
#include <cuda_bf16.h>

#define H      2048
#define E      64
#define NTOK   16384
#define TM     128
#define KT     64
#define NBLK   128
#define NKT    32

typedef unsigned int u32;

// -------- device scratch (allocation-free) --------
__device__ __align__(16) unsigned char g_Wh[NKT * 8192];
__device__ __align__(16) unsigned char g_Wm[NKT * 8192];
__device__ __align__(16) unsigned char g_Wl[NKT * 8192];
__device__ float g_part_load[NBLK * E];
__device__ float g_part_z[NBLK];
__device__ unsigned int g_arrive = 0;

#define SWZ(o) ((o) ^ (((o) >> 3) & 0x70))

__device__ __forceinline__ u32 smem_u32(const void* p) {
    u32 a;
    asm("{ .reg .u64 t; cvta.to.shared.u64 t, %1; cvt.u32.u64 %0, t; }" : "=r"(a) : "l"(p));
    return a;
}

#define CP16(dst, src) \
    asm volatile("cp.async.cg.shared.global [%0], [%1], 16;" :: "r"(dst), "l"(src) : "memory")
#define CP_COMMIT() asm volatile("cp.async.commit_group;" ::: "memory")
#define CP_WAIT0()  asm volatile("cp.async.wait_group 0;" ::: "memory")

#define LDSM4(r0, r1, r2, r3, addr) \
    asm volatile("ldmatrix.sync.aligned.m8n8.x4.shared.b16 {%0,%1,%2,%3}, [%4];" \
        : "=r"(r0), "=r"(r1), "=r"(r2), "=r"(r3) : "r"(addr))

#define MMA(d, a, b0, b1) \
    asm volatile("mma.sync.aligned.m16n8k16.row.col.f32.bf16.bf16.f32 " \
        "{%0,%1,%2,%3}, {%4,%5,%6,%7}, {%8,%9}, {%0,%1,%2,%3};" \
        : "+f"((d)[0]), "+f"((d)[1]), "+f"((d)[2]), "+f"((d)[3]) \
        : "r"((a)[0]), "r"((a)[1]), "r"((a)[2]), "r"((a)[3]), "r"(b0), "r"(b1))

// 3-way bf16 split of a float pair (residuals exact in fp32)
__device__ __forceinline__ void split3(float a, float b, u32& h, u32& m, u32& l) {
    __nv_bfloat162 hb = __floats2bfloat162_rn(a, b);
    float2 hf = __bfloat1622float2(hb);
    float ra = a - hf.x, rb = b - hf.y;
    __nv_bfloat162 mb = __floats2bfloat162_rn(ra, rb);
    float2 mf = __bfloat1622float2(mb);
    __nv_bfloat162 lb = __floats2bfloat162_rn(ra - mf.x, rb - mf.y);
    h = *(u32*)&hb; m = *(u32*)&mb; l = *(u32*)&lb;
}

// -------- prep: split + pre-swizzle W into per-tile bf16 arrays --------
__global__ __launch_bounds__(256) void prep_kernel(const float* __restrict__ W) {
    int e = blockIdx.x;
    int t = threadIdx.x;
    int k0 = t * 8;
    int kt = k0 >> 6;
    int c  = k0 & 63;
    const float4* src = (const float4*)(W + (size_t)e * H + k0);
    float4 a = src[0], b = src[1];
    uint4 Hv, Mv, Lv;
    split3(a.x, a.y, Hv.x, Mv.x, Lv.x);
    split3(a.z, a.w, Hv.y, Mv.y, Lv.y);
    split3(b.x, b.y, Hv.z, Mv.z, Lv.z);
    split3(b.z, b.w, Hv.w, Mv.w, Lv.w);
    u32 off = kt * 8192 + SWZ((u32)(e * 128 + c * 2));
    *(uint4*)(g_Wh + off) = Hv;
    *(uint4*)(g_Wm + off) = Mv;
    *(uint4*)(g_Wl + off) = Lv;
}

// ---- per-tile compute: 4 k16-chunks x (12 LDSM.x4 + 48 HMMA) ----
__device__ __forceinline__ void compute_tile(
    const float2* xq, u32 smBbase, float (*acc)[4], int rowpart, int kb16)
{
    #pragma unroll
    for (int c = 0; c < 4; c++) {
        u32 ah[4], am[4], al[4];
        #pragma unroll
        for (int j = 0; j < 4; j++) {
            float2 p = xq[c * 4 + j];
            split3(p.x, p.y, ah[j], am[j], al[j]);
        }
        u32 b[16];
        // split h of B: products hh, mh, lh
        #pragma unroll
        for (int g = 0; g < 4; g++) {
            u32 off = (u32)((g * 16 + rowpart) * 128 + c * 32 + kb16);
            LDSM4(b[4*g], b[4*g+1], b[4*g+2], b[4*g+3], smBbase + SWZ(off));
        }
        #pragma unroll
        for (int g = 0; g < 4; g++) {
            MMA(acc[2*g],   ah, b[4*g],   b[4*g+1]);
            MMA(acc[2*g+1], ah, b[4*g+2], b[4*g+3]);
            MMA(acc[2*g],   am, b[4*g],   b[4*g+1]);
            MMA(acc[2*g+1], am, b[4*g+2], b[4*g+3]);
            MMA(acc[2*g],   al, b[4*g],   b[4*g+1]);
            MMA(acc[2*g+1], al, b[4*g+2], b[4*g+3]);
        }
        // split m of B: products hm, mm
        #pragma unroll
        for (int g = 0; g < 4; g++) {
            u32 off = (u32)((g * 16 + rowpart) * 128 + c * 32 + kb16);
            LDSM4(b[4*g], b[4*g+1], b[4*g+2], b[4*g+3], smBbase + 8192 + SWZ(off));
        }
        #pragma unroll
        for (int g = 0; g < 4; g++) {
            MMA(acc[2*g],   ah, b[4*g],   b[4*g+1]);
            MMA(acc[2*g+1], ah, b[4*g+2], b[4*g+3]);
            MMA(acc[2*g],   am, b[4*g],   b[4*g+1]);
            MMA(acc[2*g+1], am, b[4*g+2], b[4*g+3]);
        }
        // split l of B: product hl
        #pragma unroll
        for (int g = 0; g < 4; g++) {
            u32 off = (u32)((g * 16 + rowpart) * 128 + c * 32 + kb16);
            LDSM4(b[4*g], b[4*g+1], b[4*g+2], b[4*g+3], smBbase + 16384 + SWZ(off));
        }
        #pragma unroll
        for (int g = 0; g < 4; g++) {
            MMA(acc[2*g],   ah, b[4*g],   b[4*g+1]);
            MMA(acc[2*g+1], ah, b[4*g+2], b[4*g+3]);
        }
    }
}

// load this lane's A-fragment source floats for one k-tile (16 float2)
__device__ __forceinline__ void load_x(
    const float* __restrict__ x, int rowBase, int w, int lane, int kt, float2* dst)
{
    const float* bl = x + (size_t)(rowBase + w * 16 + (lane >> 2)) * H + kt * 64 + (lane & 3) * 2;
    const float* bh = bl + 8 * H;
    #pragma unroll
    for (int c = 0; c < 4; c++) {
        dst[c*4+0] = *(const float2*)(bl + c * 16);
        dst[c*4+1] = *(const float2*)(bh + c * 16);
        dst[c*4+2] = *(const float2*)(bl + c * 16 + 8);
        dst[c*4+3] = *(const float2*)(bh + c * 16 + 8);
    }
}

// stage B splits for tile kt into smem buffer (24576 B)
__device__ __forceinline__ void stage_B(int kt, u32 smDst, int tid) {
    u32 d = smDst + tid * 32;
    const unsigned char* s;
    s = g_Wh + kt * 8192 + tid * 32; CP16(d, s);          CP16(d + 16, s + 16);
    s = g_Wm + kt * 8192 + tid * 32; CP16(d + 8192, s);   CP16(d + 8192 + 16, s + 16);
    s = g_Wl + kt * 8192 + tid * 32; CP16(d + 16384, s);  CP16(d + 16384 + 16, s + 16);
}

__device__ __forceinline__ void token_epilogue(
    const float* lg, int lane, int gt, float* out, int out_size,
    float& z_accum, float* comb)
{
    float m1 = -1e30f, m2 = -1e30f; int i1 = 0, i2 = 0;
    #pragma unroll
    for (int j = 0; j < 16; j++) {
        int e = (j >> 1) * 8 + (lane & 3) * 2 + (j & 1);
        float v = lg[j];
        if (v > m1) { m2 = m1; i2 = i1; m1 = v; i1 = e; }
        else if (v > m2) { m2 = v; i2 = e; }
    }
    #pragma unroll
    for (int off = 1; off <= 2; off <<= 1) {
        float om1 = __shfl_xor_sync(0xFFFFFFFFu, m1, off);
        float om2 = __shfl_xor_sync(0xFFFFFFFFu, m2, off);
        int   oi1 = __shfl_xor_sync(0xFFFFFFFFu, i1, off);
        int   oi2 = __shfl_xor_sync(0xFFFFFFFFu, i2, off);
        if (om1 > m1) {
            float t2; int tj2;
            if (m1 > om2) { t2 = m1; tj2 = i1; } else { t2 = om2; tj2 = oi2; }
            m1 = om1; i1 = oi1; m2 = t2; i2 = tj2;
        } else if (om1 > m2) { m2 = om1; i2 = oi1; }
    }
    float s = 0.0f, ex[16];
    #pragma unroll
    for (int j = 0; j < 16; j++) { ex[j] = __expf(lg[j] - m1); s += ex[j]; }
    s += __shfl_xor_sync(0xFFFFFFFFu, s, 1);
    s += __shfl_xor_sync(0xFFFFFFFFu, s, 2);
    float invS = 1.0f / s;
    #pragma unroll
    for (int j = 0; j < 16; j++) comb[j] += ex[j] * invS;
    if ((lane & 3) == 0) {
        float lse = m1 + __logf(s);
        z_accum += lse * lse;
        // softmax over the top-2 PROBABILITIES (p1 = 1/S, p2 = exp(m2-m1)/S)
        float p1 = invS, p2 = __expf(m2 - m1) * invS;
        float r2 = 1.0f / (1.0f + __expf(p1 - p2));
        float r1 = 1.0f - r2;
        if (2 * gt + 1 < out_size) { out[2 * gt] = r1; out[2 * gt + 1] = r2; }
        int ib = 2 * NTOK;
        if (ib + 2 * gt + 1 < out_size) {
            out[ib + 2 * gt] = (float)i1; out[ib + 2 * gt + 1] = (float)i2;
        }
    }
}

__global__ __launch_bounds__(256, 1) void gate_kernel(
    const float* __restrict__ x, float* __restrict__ out, int out_size)
{
    extern __shared__ __align__(128) unsigned char smc[];  // 2 x 24576 B buffers
    __shared__ float wsum[8][E];
    __shared__ float wz[8];
    __shared__ float redsm[256];
    __shared__ float zred2[4];
    __shared__ unsigned int lastflag;

    const u32 smB = smem_u32(smc);
    const int tid = threadIdx.x;
    const int w = tid >> 5;
    const int lane = tid & 31;
    const int blk = blockIdx.x;
    const int rowBase = blk * TM;

    const int rowpart = ((lane >> 4) & 1) * 8 + (lane & 7);
    const int kb16    = ((lane >> 3) & 1) * 16;

    float acc[8][4];
    #pragma unroll
    for (int n = 0; n < 8; n++)
        #pragma unroll
        for (int j = 0; j < 4; j++) acc[n][j] = 0.0f;

    float2 xq0[16], xq1[16];

    // prologue: stage tile 0
    stage_B(0, smB, tid);
    CP_COMMIT();
    load_x(x, rowBase, w, lane, 0, xq0);
    CP_WAIT0();
    __syncthreads();

    for (int kt = 0; kt < NKT; kt += 2) {
        // prefetch kt+1 into buffer 1
        stage_B(kt + 1, smB + 24576, tid);
        CP_COMMIT();
        load_x(x, rowBase, w, lane, kt + 1, xq1);

        compute_tile(xq0, smB, acc, rowpart, kb16);

        CP_WAIT0();
        __syncthreads();

        if (kt + 2 < NKT) {
            stage_B(kt + 2, smB, tid);
            CP_COMMIT();
            load_x(x, rowBase, w, lane, kt + 2, xq0);
        }

        compute_tile(xq1, smB + 24576, acc, rowpart, kb16);

        if (kt + 2 < NKT) {
            CP_WAIT0();
            __syncthreads();
        }
    }

    // -------- epilogue --------
    float lgl[16], lgh[16];
    #pragma unroll
    for (int n = 0; n < 8; n++) {
        lgl[2*n] = acc[n][0]; lgl[2*n+1] = acc[n][1];
        lgh[2*n] = acc[n][2]; lgh[2*n+1] = acc[n][3];
    }

    float comb[16];
    #pragma unroll
    for (int j = 0; j < 16; j++) comb[j] = 0.0f;
    float zacc = 0.0f;

    int gt_lo = rowBase + w * 16 + (lane >> 2);
    token_epilogue(lgl, lane, gt_lo,     out, out_size, zacc, comb);
    token_epilogue(lgh, lane, gt_lo + 8, out, out_size, zacc, comb);

    // warp reduce expert prob sums across quads (tokens)
    #pragma unroll
    for (int off = 4; off <= 16; off <<= 1)
        #pragma unroll
        for (int j = 0; j < 16; j++)
            comb[j] += __shfl_down_sync(0xFFFFFFFFu, comb[j], off);
    if (lane < 4) {
        #pragma unroll
        for (int j = 0; j < 16; j++)
            wsum[w][(j >> 1) * 8 + lane * 2 + (j & 1)] = comb[j];
    }
    float zs = zacc;  // nonzero only on quad leaders
    #pragma unroll
    for (int off = 16; off > 0; off >>= 1)
        zs += __shfl_down_sync(0xFFFFFFFFu, zs, off);
    if (lane == 0) wz[w] = zs;
    __syncthreads();

    if (tid < E) {
        float s = 0.0f;
        #pragma unroll
        for (int ww = 0; ww < 8; ww++) s += wsum[ww][tid];
        g_part_load[blk * E + tid] = s;
    }
    if (tid == 0) {
        float z = 0.0f;
        #pragma unroll
        for (int ww = 0; ww < 8; ww++) z += wz[ww];
        g_part_z[blk] = z;
    }

    // -------- last-block loss reduction --------
    __threadfence();
    __syncthreads();
    if (tid == 0) {
        unsigned int v = atomicAdd(&g_arrive, 1u);
        lastflag = (v == NBLK - 1) ? 1u : 0u;
    }
    __syncthreads();
    if (lastflag) {
        __threadfence();
        int qq = tid >> 6, e = tid & 63;
        float sacc = 0.0f;
        for (int b = qq * 32; b < qq * 32 + 32; b++) sacc += g_part_load[b * E + e];
        redsm[tid] = sacc;
        __syncthreads();
        if (tid < E) {
            float S = redsm[tid] + redsm[64 + tid] + redsm[128 + tid] + redsm[192 + tid];
            float d = S * (1.0f / (float)NTOK) - (1.0f / (float)E);
            redsm[tid] = d * d;
        }
        __syncthreads();
        if (tid < 32) {
            float v = redsm[tid] + redsm[tid + 32];
            #pragma unroll
            for (int o = 16; o > 0; o >>= 1) v += __shfl_down_sync(0xFFFFFFFFu, v, o);
            if (tid == 0) redsm[0] = v;  // lb sum
        }
        if (tid >= 128 && tid < 256) {
            float zv = g_part_z[tid - 128];
            #pragma unroll
            for (int o = 16; o > 0; o >>= 1) zv += __shfl_down_sync(0xFFFFFFFFu, zv, o);
            if (((tid - 128) & 31) == 0) zred2[(tid - 128) >> 5] = zv;
        }
        __syncthreads();
        if (tid == 0) {
            float z = zred2[0] + zred2[1] + zred2[2] + zred2[3];
            float total = 0.01f * redsm[0] + 1e-4f * (z / (float)NTOK);
            if (out_size > 4 * NTOK) out[4 * NTOK] = total;
            g_arrive = 0;
        }
    }
}

extern "C" void kernel_launch(void* const* d_in, const int* in_sizes, int n_in,
                              void* d_out, int out_size)
{
    const float* x = (const float*)d_in[0];
    const float* W = (const float*)d_in[1];
    float* out = (float*)d_out;

    cudaFuncSetAttribute(gate_kernel, cudaFuncAttributeMaxDynamicSharedMemorySize, 49152);
    prep_kernel<<<E, 256>>>(W);
    gate_kernel<<<NBLK, 256, 49152>>>(x, out, out_size);
}

// round 6
// speedup vs baseline: 1.8761x; 1.0010x over previous
#include <cuda_runtime.h>
#include <cuda_bf16.h>

#define H      2048
#define E      64
#define NTOK   16384
#define TM     128
#define KT     64
#define NBLK   128
#define NKT    32

typedef unsigned int u32;

// -------- device scratch (allocation-free) --------
__device__ __align__(16) unsigned char g_Wh[NKT * 8192];
__device__ __align__(16) unsigned char g_Wm[NKT * 8192];
__device__ __align__(16) unsigned char g_Wl[NKT * 8192];
__device__ float g_part_load[NBLK * E];
__device__ float g_part_z[NBLK];
__device__ unsigned int g_arrive = 0;

#define SWZ(o) ((o) ^ (((o) >> 3) & 0x70))

__device__ __forceinline__ u32 smem_u32(const void* p) {
    u32 a;
    asm("{ .reg .u64 t; cvta.to.shared.u64 t, %1; cvt.u32.u64 %0, t; }" : "=r"(a) : "l"(p));
    return a;
}

#define CP16(dst, src) \
    asm volatile("cp.async.cg.shared.global [%0], [%1], 16;" :: "r"(dst), "l"(src) : "memory")
#define CP_COMMIT() asm volatile("cp.async.commit_group;" ::: "memory")
#define CP_WAIT0()  asm volatile("cp.async.wait_group 0;" ::: "memory")

#define LDSM4(r0, r1, r2, r3, addr) \
    asm volatile("ldmatrix.sync.aligned.m8n8.x4.shared.b16 {%0,%1,%2,%3}, [%4];" \
        : "=r"(r0), "=r"(r1), "=r"(r2), "=r"(r3) : "r"(addr))

#define MMA(d, a, b0, b1) \
    asm volatile("mma.sync.aligned.m16n8k16.row.col.f32.bf16.bf16.f32 " \
        "{%0,%1,%2,%3}, {%4,%5,%6,%7}, {%8,%9}, {%0,%1,%2,%3};" \
        : "+f"((d)[0]), "+f"((d)[1]), "+f"((d)[2]), "+f"((d)[3]) \
        : "r"((a)[0]), "r"((a)[1]), "r"((a)[2]), "r"((a)[3]), "r"(b0), "r"(b1))

// 3-way bf16 split of a float pair (residuals exact in fp32)
__device__ __forceinline__ void split3(float a, float b, u32& h, u32& m, u32& l) {
    __nv_bfloat162 hb = __floats2bfloat162_rn(a, b);
    float2 hf = __bfloat1622float2(hb);
    float ra = a - hf.x, rb = b - hf.y;
    __nv_bfloat162 mb = __floats2bfloat162_rn(ra, rb);
    float2 mf = __bfloat1622float2(mb);
    __nv_bfloat162 lb = __floats2bfloat162_rn(ra - mf.x, rb - mf.y);
    h = *(u32*)&hb; m = *(u32*)&mb; l = *(u32*)&lb;
}

// -------- prep: split + pre-swizzle W into per-tile bf16 arrays --------
__global__ __launch_bounds__(256) void prep_kernel(const float* __restrict__ W) {
    int e = blockIdx.x;
    int t = threadIdx.x;
    int k0 = t * 8;
    int kt = k0 >> 6;
    int c  = k0 & 63;
    const float4* src = (const float4*)(W + (size_t)e * H + k0);
    float4 a = src[0], b = src[1];
    uint4 Hv, Mv, Lv;
    split3(a.x, a.y, Hv.x, Mv.x, Lv.x);
    split3(a.z, a.w, Hv.y, Mv.y, Lv.y);
    split3(b.x, b.y, Hv.z, Mv.z, Lv.z);
    split3(b.z, b.w, Hv.w, Mv.w, Lv.w);
    u32 off = kt * 8192 + SWZ((u32)(e * 128 + c * 2));
    *(uint4*)(g_Wh + off) = Hv;
    *(uint4*)(g_Wm + off) = Mv;
    *(uint4*)(g_Wl + off) = Lv;
}

// one n-sweep: 8 MMAs over 8 distinct accumulators (RAW distance = 8)
__device__ __forceinline__ void pass8(float (*acc)[4], const u32* a, const u32* b) {
    #pragma unroll
    for (int g = 0; g < 4; g++) {
        MMA(acc[2*g],   a, b[4*g],   b[4*g+1]);
        MMA(acc[2*g+1], a, b[4*g+2], b[4*g+3]);
    }
}
__device__ __forceinline__ void ldsm_grp(u32* b, u32 base, int c, int rowpart, int kb16) {
    #pragma unroll
    for (int g = 0; g < 4; g++) {
        u32 off = (u32)((g * 16 + rowpart) * 128 + c * 32 + kb16);
        LDSM4(b[4*g], b[4*g+1], b[4*g+2], b[4*g+3], base + SWZ(off));
    }
}

// ---- per-tile compute, product-major MMA order + ping-pong B buffers ----
// chunk body: X holds h-split(c) on entry; leaves h-split(c+1) in Y.
#define CHUNK(c, X, Y) do {                                                   \
    u32 ah[4], am[4], al[4];                                                  \
    _Pragma("unroll")                                                         \
    for (int j = 0; j < 4; j++) {                                             \
        float2 p = xq[(c) * 4 + j];                                           \
        split3(p.x, p.y, ah[j], am[j], al[j]);                                \
    }                                                                         \
    ldsm_grp(Y, smBbase + 8192, (c), rowpart, kb16);      /* m-split */       \
    pass8(acc, ah, X); pass8(acc, am, X); pass8(acc, al, X);  /* x * Wh */    \
    ldsm_grp(X, smBbase + 16384, (c), rowpart, kb16);     /* l-split */       \
    pass8(acc, ah, Y); pass8(acc, am, Y);                     /* x * Wm */    \
    if ((c) < 3) ldsm_grp(Y, smBbase, (c) + 1, rowpart, kb16); /* next h */   \
    pass8(acc, ah, X);                                        /* xh * Wl */   \
} while (0)

__device__ __forceinline__ void compute_tile(
    const float2* xq, u32 smBbase, float (*acc)[4], int rowpart, int kb16)
{
    u32 b0[16], b1[16];
    ldsm_grp(b0, smBbase, 0, rowpart, kb16);   // h-split, chunk 0
    CHUNK(0, b0, b1);
    CHUNK(1, b1, b0);
    CHUNK(2, b0, b1);
    CHUNK(3, b1, b0);
}

// load this lane's A-fragment source floats for one k-tile (16 float2)
__device__ __forceinline__ void load_x(
    const float* __restrict__ x, int rowBase, int w, int lane, int kt, float2* dst)
{
    const float* bl = x + (size_t)(rowBase + w * 16 + (lane >> 2)) * H + kt * 64 + (lane & 3) * 2;
    const float* bh = bl + 8 * H;
    #pragma unroll
    for (int c = 0; c < 4; c++) {
        dst[c*4+0] = *(const float2*)(bl + c * 16);
        dst[c*4+1] = *(const float2*)(bh + c * 16);
        dst[c*4+2] = *(const float2*)(bl + c * 16 + 8);
        dst[c*4+3] = *(const float2*)(bh + c * 16 + 8);
    }
}

// stage B splits for tile kt into smem buffer (24576 B)
__device__ __forceinline__ void stage_B(int kt, u32 smDst, int tid) {
    u32 d = smDst + tid * 32;
    const unsigned char* s;
    s = g_Wh + kt * 8192 + tid * 32; CP16(d, s);          CP16(d + 16, s + 16);
    s = g_Wm + kt * 8192 + tid * 32; CP16(d + 8192, s);   CP16(d + 8192 + 16, s + 16);
    s = g_Wl + kt * 8192 + tid * 32; CP16(d + 16384, s);  CP16(d + 16384 + 16, s + 16);
}

__device__ __forceinline__ void token_epilogue(
    const float* lg, int lane, int gt, float* out, int out_size,
    float& z_accum, float* comb)
{
    float m1 = -1e30f, m2 = -1e30f; int i1 = 0, i2 = 0;
    #pragma unroll
    for (int j = 0; j < 16; j++) {
        int e = (j >> 1) * 8 + (lane & 3) * 2 + (j & 1);
        float v = lg[j];
        if (v > m1) { m2 = m1; i2 = i1; m1 = v; i1 = e; }
        else if (v > m2) { m2 = v; i2 = e; }
    }
    #pragma unroll
    for (int off = 1; off <= 2; off <<= 1) {
        float om1 = __shfl_xor_sync(0xFFFFFFFFu, m1, off);
        float om2 = __shfl_xor_sync(0xFFFFFFFFu, m2, off);
        int   oi1 = __shfl_xor_sync(0xFFFFFFFFu, i1, off);
        int   oi2 = __shfl_xor_sync(0xFFFFFFFFu, i2, off);
        if (om1 > m1) {
            float t2; int tj2;
            if (m1 > om2) { t2 = m1; tj2 = i1; } else { t2 = om2; tj2 = oi2; }
            m1 = om1; i1 = oi1; m2 = t2; i2 = tj2;
        } else if (om1 > m2) { m2 = om1; i2 = oi1; }
    }
    float s = 0.0f, ex[16];
    #pragma unroll
    for (int j = 0; j < 16; j++) { ex[j] = __expf(lg[j] - m1); s += ex[j]; }
    s += __shfl_xor_sync(0xFFFFFFFFu, s, 1);
    s += __shfl_xor_sync(0xFFFFFFFFu, s, 2);
    float invS = 1.0f / s;
    #pragma unroll
    for (int j = 0; j < 16; j++) comb[j] += ex[j] * invS;
    if ((lane & 3) == 0) {
        float lse = m1 + __logf(s);
        z_accum += lse * lse;
        // softmax over the top-2 PROBABILITIES (p1 = 1/S, p2 = exp(m2-m1)/S)
        float p1 = invS, p2 = __expf(m2 - m1) * invS;
        float r2 = 1.0f / (1.0f + __expf(p1 - p2));
        float r1 = 1.0f - r2;
        if (2 * gt + 1 < out_size) { out[2 * gt] = r1; out[2 * gt + 1] = r2; }
        int ib = 2 * NTOK;
        if (ib + 2 * gt + 1 < out_size) {
            out[ib + 2 * gt] = (float)i1; out[ib + 2 * gt + 1] = (float)i2;
        }
    }
}

__global__ __launch_bounds__(256, 1) void gate_kernel(
    const float* __restrict__ x, float* __restrict__ out, int out_size)
{
    extern __shared__ __align__(128) unsigned char smc[];  // 2 x 24576 B buffers
    __shared__ float wsum[8][E];
    __shared__ float wz[8];
    __shared__ float redsm[256];
    __shared__ float zred2[4];
    __shared__ unsigned int lastflag;

    const u32 smB = smem_u32(smc);
    const int tid = threadIdx.x;
    const int w = tid >> 5;
    const int lane = tid & 31;
    const int blk = blockIdx.x;
    const int rowBase = blk * TM;

    const int rowpart = ((lane >> 4) & 1) * 8 + (lane & 7);
    const int kb16    = ((lane >> 3) & 1) * 16;

    float acc[8][4];
    #pragma unroll
    for (int n = 0; n < 8; n++)
        #pragma unroll
        for (int j = 0; j < 4; j++) acc[n][j] = 0.0f;

    float2 xq0[16], xq1[16];

    // prologue: stage tile 0
    stage_B(0, smB, tid);
    CP_COMMIT();
    load_x(x, rowBase, w, lane, 0, xq0);
    CP_WAIT0();
    __syncthreads();

    for (int kt = 0; kt < NKT; kt += 2) {
        // prefetch kt+1 into buffer 1
        stage_B(kt + 1, smB + 24576, tid);
        CP_COMMIT();
        load_x(x, rowBase, w, lane, kt + 1, xq1);

        compute_tile(xq0, smB, acc, rowpart, kb16);

        CP_WAIT0();
        __syncthreads();

        if (kt + 2 < NKT) {
            stage_B(kt + 2, smB, tid);
            CP_COMMIT();
            load_x(x, rowBase, w, lane, kt + 2, xq0);
        }

        compute_tile(xq1, smB + 24576, acc, rowpart, kb16);

        if (kt + 2 < NKT) {
            CP_WAIT0();
            __syncthreads();
        }
    }

    // -------- epilogue --------
    float lgl[16], lgh[16];
    #pragma unroll
    for (int n = 0; n < 8; n++) {
        lgl[2*n] = acc[n][0]; lgl[2*n+1] = acc[n][1];
        lgh[2*n] = acc[n][2]; lgh[2*n+1] = acc[n][3];
    }

    float comb[16];
    #pragma unroll
    for (int j = 0; j < 16; j++) comb[j] = 0.0f;
    float zacc = 0.0f;

    int gt_lo = rowBase + w * 16 + (lane >> 2);
    token_epilogue(lgl, lane, gt_lo,     out, out_size, zacc, comb);
    token_epilogue(lgh, lane, gt_lo + 8, out, out_size, zacc, comb);

    // warp reduce expert prob sums across quads (tokens)
    #pragma unroll
    for (int off = 4; off <= 16; off <<= 1)
        #pragma unroll
        for (int j = 0; j < 16; j++)
            comb[j] += __shfl_down_sync(0xFFFFFFFFu, comb[j], off);
    if (lane < 4) {
        #pragma unroll
        for (int j = 0; j < 16; j++)
            wsum[w][(j >> 1) * 8 + lane * 2 + (j & 1)] = comb[j];
    }
    float zs = zacc;  // nonzero only on quad leaders
    #pragma unroll
    for (int off = 16; off > 0; off >>= 1)
        zs += __shfl_down_sync(0xFFFFFFFFu, zs, off);
    if (lane == 0) wz[w] = zs;
    __syncthreads();

    if (tid < E) {
        float s = 0.0f;
        #pragma unroll
        for (int ww = 0; ww < 8; ww++) s += wsum[ww][tid];
        g_part_load[blk * E + tid] = s;
    }
    if (tid == 0) {
        float z = 0.0f;
        #pragma unroll
        for (int ww = 0; ww < 8; ww++) z += wz[ww];
        g_part_z[blk] = z;
    }

    // -------- last-block loss reduction --------
    __threadfence();
    __syncthreads();
    if (tid == 0) {
        unsigned int v = atomicAdd(&g_arrive, 1u);
        lastflag = (v == NBLK - 1) ? 1u : 0u;
    }
    __syncthreads();
    if (lastflag) {
        __threadfence();
        int qq = tid >> 6, e = tid & 63;
        float sacc = 0.0f;
        for (int b = qq * 32; b < qq * 32 + 32; b++) sacc += g_part_load[b * E + e];
        redsm[tid] = sacc;
        __syncthreads();
        if (tid < E) {
            float S = redsm[tid] + redsm[64 + tid] + redsm[128 + tid] + redsm[192 + tid];
            float d = S * (1.0f / (float)NTOK) - (1.0f / (float)E);
            redsm[tid] = d * d;
        }
        __syncthreads();
        if (tid < 32) {
            float v = redsm[tid] + redsm[tid + 32];
            #pragma unroll
            for (int o = 16; o > 0; o >>= 1) v += __shfl_down_sync(0xFFFFFFFFu, v, o);
            if (tid == 0) redsm[0] = v;  // lb sum
        }
        if (tid >= 128 && tid < 256) {
            float zv = g_part_z[tid - 128];
            #pragma unroll
            for (int o = 16; o > 0; o >>= 1) zv += __shfl_down_sync(0xFFFFFFFFu, zv, o);
            if (((tid - 128) & 31) == 0) zred2[(tid - 128) >> 5] = zv;
        }
        __syncthreads();
        if (tid == 0) {
            float z = zred2[0] + zred2[1] + zred2[2] + zred2[3];
            float total = 0.01f * redsm[0] + 1e-4f * (z / (float)NTOK);
            if (out_size > 4 * NTOK) out[4 * NTOK] = total;
            g_arrive = 0;
        }
    }
}

extern "C" void kernel_launch(void* const* d_in, const int* in_sizes, int n_in,
                              void* d_out, int out_size)
{
    const float* x = (const float*)d_in[0];
    const float* W = (const float*)d_in[1];
    float* out = (float*)d_out;

    cudaFuncSetAttribute(gate_kernel, cudaFuncAttributeMaxDynamicSharedMemorySize, 49152);
    prep_kernel<<<E, 256>>>(W);
    gate_kernel<<<NBLK, 256, 49152>>>(x, out, out_size);
}